// round 1
// baseline (speedup 1.0000x reference)
#include <cuda_runtime.h>
#include <math.h>

#define C_DIM 384
#define G_DIM 383
#define M_DIM 384
#define EPS_F 1e-5f

// Scratch (no allocation allowed in kernel_launch)
__device__ float g_sum[G_DIM];
__device__ float g_sumsq[G_DIM];
__device__ int   g_cnt[G_DIM];
__device__ float g_proto[M_DIM];
__device__ float g_std[M_DIM];

// ---------------- Kernel 0: zero accumulators + output ----------------
__global__ void k_zero(float* out) {
    int t = blockIdx.x * blockDim.x + threadIdx.x;
    if (t < G_DIM) { g_sum[t] = 0.f; g_sumsq[t] = 0.f; g_cnt[t] = 0; }
    if (t == 0) out[0] = 0.f;
}

// ---------------- Kernel 1: per-group count/sum/sumsq (one warp per row) ----------------
__global__ void k_accum(const float4* __restrict__ pred,
                        const int* __restrict__ tgt, int nrows) {
    int w    = (blockIdx.x * blockDim.x + threadIdx.x) >> 5;   // global warp id = row
    int lane = threadIdx.x & 31;
    if (w >= nrows) return;

    const float4* row = pred + (size_t)w * (C_DIM / 4);
    float s = 0.f, ss = 0.f;
#pragma unroll
    for (int i = 0; i < C_DIM / 128; i++) {           // 3 float4 per lane
        float4 v = __ldcs(&row[lane + 32 * i]);
        s  += (v.x + v.y) + (v.z + v.w);
        ss  = fmaf(v.x, v.x, ss);
        ss  = fmaf(v.y, v.y, ss);
        ss  = fmaf(v.z, v.z, ss);
        ss  = fmaf(v.w, v.w, ss);
    }
#pragma unroll
    for (int o = 16; o; o >>= 1) {
        s  += __shfl_down_sync(0xffffffffu, s,  o);
        ss += __shfl_down_sync(0xffffffffu, ss, o);
    }
    if (lane == 0) {
        int g = tgt[w];
        atomicAdd(&g_sum[g],   s);
        atomicAdd(&g_sumsq[g], ss);
        atomicAdd(&g_cnt[g],   1);
    }
}

// ---------------- Kernel 2: mean / std per group ----------------
__global__ void k_stats() {
    int g = threadIdx.x;
    if (g >= M_DIM) return;
    float mean = 0.f, sd = 0.f;
    if (g < G_DIM) {
        float n = (float)g_cnt[g];
        if (n > 0.f) {
            float cnt = n * (float)C_DIM;
            float sum = g_sum[g];
            mean = sum / cnt;
            float ssq = g_sumsq[g] - sum * mean;   // = sumsq - sum^2/cnt
            if (ssq < 0.f) ssq = 0.f;
            sd = (n > 1.f) ? sqrtf(ssq / fmaxf(cnt - 1.f, 1.f)) : 0.f;
        }
    }
    g_proto[g] = mean;   // slot 383 stays 0 (padded object slot)
    g_std[g]   = sd;
}

// ---------------- Kernel 3: masked mean over the M^3 cube ----------------
// V[x,a,b] = w / (sqrtC*|p_b-p_a| + w + eps),  w = (std_a+std_b)*u[x,a],
// u[x,a] = |p_x-p_a| / (sqrtC*|p_x-p_a| + eps).  Mask: b > a.
// Thread <-> (x,a) pair, inner loop over b.  a = t % M so warps have
// near-uniform loop lengths.
__global__ void k_reduce(float* __restrict__ out) {
    __shared__ float sp[M_DIM];
    __shared__ float ssd[M_DIM];
    __shared__ float red[8];

    int tid = threadIdx.x;
    for (int i = tid; i < M_DIM; i += blockDim.x) {
        sp[i]  = g_proto[i];
        ssd[i] = g_std[i];
    }
    __syncthreads();

    const float SQC = 19.595917942265423f;  // sqrtf(384)
    int t = blockIdx.x * blockDim.x + tid;  // t in [0, M*M), grid sized exactly
    int a = t % M_DIM;
    int x = t / M_DIM;

    float pa  = sp[a];
    float txa = fabsf(sp[x] - pa);
    float u   = __fdividef(txa, fmaf(SQC, txa, EPS_F));  // 0 when x==a
    float q   = ssd[a] * u;

    float acc = 0.f;
    for (int b = a + 1; b < M_DIM; b++) {
        float w   = fmaf(ssd[b], u, q);                       // (sa+sb)*u
        float den = fmaf(SQC, fabsf(sp[b] - pa), w + EPS_F);  // norm + s + eps
        acc += __fdividef(w, den);
    }

    // block reduction
#pragma unroll
    for (int o = 16; o; o >>= 1) acc += __shfl_down_sync(0xffffffffu, acc, o);
    if ((tid & 31) == 0) red[tid >> 5] = acc;
    __syncthreads();
    if (tid < 8) {
        float v = red[tid];
#pragma unroll
        for (int o = 4; o; o >>= 1) v += __shfl_down_sync(0x000000ffu, v, o);
        if (tid == 0) {
            const float inv_m3 = 1.0f / ((float)M_DIM * (float)M_DIM * (float)M_DIM);
            atomicAdd(out, v * inv_m3);
        }
    }
}

extern "C" void kernel_launch(void* const* d_in, const int* in_sizes, int n_in,
                              void* d_out, int out_size) {
    const float* pred = (const float*)d_in[0];
    const int*   tgt  = (const int*)d_in[1];
    float*       out  = (float*)d_out;
    int nrows = in_sizes[1];                // 200000

    k_zero<<<2, 256>>>(out);

    int blocks = (nrows * 32 + 255) / 256;  // one warp per row, 8 warps/block
    k_accum<<<blocks, 256>>>((const float4*)pred, tgt, nrows);

    k_stats<<<1, M_DIM>>>();

    k_reduce<<<(M_DIM * M_DIM) / 256, 256>>>(out);
}